// round 2
// baseline (speedup 1.0000x reference)
#include <cuda_runtime.h>
#include <cuda_bf16.h>
#include <cstddef>

#define N_NODES 30000
#define E_EDGES 480000
#define HID 256
#define HEADS 8
#define OUTC 32
#define NLAYERS 6
#define NODE_IN 13
#define EDGE_IN 10

// ---------------- static device scratch (no allocations allowed) ----------------
__device__ float g_h   [N_NODES * HID];
__device__ float g_xl  [N_NODES * HID];
__device__ float g_xr  [N_NODES * HID];
__device__ float g_ea  [(size_t)E_EDGES * HID];
__device__ float g_eb  [(size_t)E_EDGES * HID];
__device__ float g_ep  [(size_t)E_EDGES * HID];
__device__ float g_log [(size_t)E_EDGES * HEADS];
__device__ float g_mlp [N_NODES * 128];
__device__ int   g_deg [N_NODES];
__device__ int   g_rowoff[N_NODES + 1];
__device__ int   g_cursor[N_NODES];
__device__ int   g_perm[E_EDGES];

// ---------------- CSR build ----------------
__global__ void zero_int_kernel(int* p, int n) {
    int i = blockIdx.x * blockDim.x + threadIdx.x;
    if (i < n) p[i] = 0;
}

__global__ void count_kernel(const int* __restrict__ dst, int* __restrict__ deg) {
    int e = blockIdx.x * blockDim.x + threadIdx.x;
    if (e < E_EDGES) atomicAdd(&deg[dst[e]], 1);
}

__global__ void scan_kernel(const int* __restrict__ deg, int* __restrict__ rowoff,
                            int* __restrict__ cursor) {
    __shared__ int s[1024];
    int tid = threadIdx.x;
    const int CH = (N_NODES + 1023) / 1024;  // 30
    int base = tid * CH;
    int sum = 0;
    for (int i = 0; i < CH; i++) {
        int idx = base + i;
        if (idx < N_NODES) sum += deg[idx];
    }
    s[tid] = sum;
    __syncthreads();
    for (int off = 1; off < 1024; off <<= 1) {
        int v = (tid >= off) ? s[tid - off] : 0;
        __syncthreads();
        s[tid] += v;
        __syncthreads();
    }
    int run = s[tid] - sum;  // exclusive prefix
    for (int i = 0; i < CH; i++) {
        int idx = base + i;
        if (idx < N_NODES) {
            rowoff[idx] = run;
            cursor[idx] = run;
            run += deg[idx];
        }
    }
    if (tid == 1023) rowoff[N_NODES] = run;
}

__global__ void scatter_kernel(const int* __restrict__ dst, int* __restrict__ cursor,
                               int* __restrict__ perm) {
    int e = blockIdx.x * blockDim.x + threadIdx.x;
    if (e < E_EDGES) {
        int p = atomicAdd(&cursor[dst[e]], 1);
        perm[p] = e;
    }
}

// ---------------- input projections (small K) ----------------
__global__ void node_in_kernel(const float* __restrict__ x, const float* __restrict__ W,
                               const float* __restrict__ b, float* __restrict__ h) {
    int idx = blockIdx.x * blockDim.x + threadIdx.x;
    if (idx >= N_NODES * HID) return;
    int r = idx >> 8, c = idx & 255;
    float s = b[c];
#pragma unroll
    for (int k = 0; k < NODE_IN; k++) s += x[r * NODE_IN + k] * W[k * HID + c];
    h[idx] = s;
}

__global__ void edge_in_kernel(const float* __restrict__ ea_in, const float* __restrict__ W,
                               const float* __restrict__ b, float* __restrict__ ea) {
    size_t idx = (size_t)blockIdx.x * blockDim.x + threadIdx.x;
    if (idx >= (size_t)E_EDGES * HID) return;
    size_t r = idx >> 8;
    int c = (int)(idx & 255);
    float s = b[c];
#pragma unroll
    for (int k = 0; k < EDGE_IN; k++) s += ea_in[r * EDGE_IN + k] * W[k * HID + c];
    ea[idx] = s;
}

// ---------------- tiled fp32 GEMM with register prefetch ----------------
// C[M,Nc] = A[M,K] @ B[K,Nc] (+bias) (+leaky). Tiles: 128x128x8, 256 thr, 8x8 microtile.
#define GBM 128
#define GBN 128
#define GBK 8
__global__ __launch_bounds__(256, 2)
void gemm_kernel(const float* __restrict__ A, const float* __restrict__ B,
                 const float* __restrict__ bias, float* __restrict__ C,
                 int M, int K, int Nc, int act) {
    __shared__ float As[GBK][GBM];
    __shared__ float Bs[GBK][GBN];
    int tid = threadIdx.x;
    int ty = tid >> 4, tx = tid & 15;          // 16 x 16 thread grid
    int rowBase = blockIdx.y * GBM;
    int colBase = blockIdx.x * GBN;

    int arow = tid >> 1, aq = tid & 1;         // A: 128 rows x 2 float4 of K
    int brow = tid >> 5, bq = tid & 31;        // B: 8 rows x 32 float4 of N

    int gr = rowBase + arow;
    bool aval = (gr < M);
    const float* Aptr = A + (size_t)(aval ? gr : 0) * K + aq * 4;
    const float* Bptr = B + (size_t)brow * Nc + colBase + bq * 4;

    float acc[8][8];
#pragma unroll
    for (int i = 0; i < 8; i++)
#pragma unroll
        for (int j = 0; j < 8; j++) acc[i][j] = 0.f;

    // preload first tile
    float4 av = aval ? *(const float4*)(Aptr) : make_float4(0.f, 0.f, 0.f, 0.f);
    float4 bv = *(const float4*)(Bptr);

    for (int k0 = 0; k0 < K; k0 += GBK) {
        As[aq * 4 + 0][arow] = av.x;
        As[aq * 4 + 1][arow] = av.y;
        As[aq * 4 + 2][arow] = av.z;
        As[aq * 4 + 3][arow] = av.w;
        *(float4*)&Bs[brow][bq * 4] = bv;
        __syncthreads();

        // prefetch next tile while computing
        if (k0 + GBK < K) {
            av = aval ? *(const float4*)(Aptr + k0 + GBK) : make_float4(0.f, 0.f, 0.f, 0.f);
            bv = *(const float4*)(Bptr + (size_t)GBK * Nc + (size_t)k0 * Nc);
        }

#pragma unroll
        for (int k = 0; k < GBK; k++) {
            float4 a0 = *(const float4*)&As[k][ty * 8];
            float4 a1 = *(const float4*)&As[k][ty * 8 + 4];
            float4 b0 = *(const float4*)&Bs[k][tx * 8];
            float4 b1 = *(const float4*)&Bs[k][tx * 8 + 4];
            float a[8] = {a0.x, a0.y, a0.z, a0.w, a1.x, a1.y, a1.z, a1.w};
            float b[8] = {b0.x, b0.y, b0.z, b0.w, b1.x, b1.y, b1.z, b1.w};
#pragma unroll
            for (int i = 0; i < 8; i++)
#pragma unroll
                for (int j = 0; j < 8; j++) acc[i][j] += a[i] * b[j];
        }
        __syncthreads();
    }

#pragma unroll
    for (int i = 0; i < 8; i++) {
        int r = rowBase + ty * 8 + i;
        if (r >= M) continue;
#pragma unroll
        for (int j = 0; j < 8; j++) {
            int c = colBase + tx * 8 + j;
            float v = acc[i][j];
            if (bias) v += bias[c];
            if (act) v = (v >= 0.f) ? v : 0.01f * v;
            C[(size_t)r * Nc + c] = v;
        }
    }
}

// ---------------- attention logits: one warp per edge ----------------
__global__ void logits_kernel(const int* __restrict__ src, const int* __restrict__ dst,
                              const float* __restrict__ xl, const float* __restrict__ xr,
                              const float* __restrict__ ep, const float* __restrict__ att_l,
                              float* __restrict__ logits) {
    __shared__ float satt[HID];
    int tid = threadIdx.x;
    satt[tid] = att_l[tid];
    __syncthreads();
    int warp = tid >> 5, lane = tid & 31;
    int e = blockIdx.x * 8 + warp;
    if (e >= E_EDGES) return;
    int s = src[e], d = dst[e];
    const float4* pl = (const float4*)(xl + (size_t)s * HID + lane * 8);
    const float4* pr = (const float4*)(xr + (size_t)d * HID + lane * 8);
    const float4* pe = (const float4*)(ep + (size_t)e * HID + lane * 8);
    float4 l0 = pl[0], l1 = pl[1];
    float4 r0 = pr[0], r1 = pr[1];
    float4 e0 = pe[0], e1 = pe[1];
    float vv[8] = {l0.x + r0.x + e0.x, l0.y + r0.y + e0.y, l0.z + r0.z + e0.z, l0.w + r0.w + e0.w,
                   l1.x + r1.x + e1.x, l1.y + r1.y + e1.y, l1.z + r1.z + e1.z, l1.w + r1.w + e1.w};
    float sum = 0.f;
#pragma unroll
    for (int j = 0; j < 8; j++) {
        float v = vv[j];
        v = (v >= 0.f) ? v : 0.2f * v;           // leaky 0.2
        sum += v * satt[lane * 8 + j];
    }
    sum += __shfl_xor_sync(0xffffffffu, sum, 1);
    sum += __shfl_xor_sync(0xffffffffu, sum, 2);
    if ((lane & 3) == 0) logits[(size_t)e * HEADS + (lane >> 2)] = sum;
}

// ---------------- fused per-node: softmax + aggregate + bias + BN + leaky + residual ----------------
__global__ void node_agg_kernel(const int* __restrict__ rowoff, const int* __restrict__ perm,
                                const int* __restrict__ src, const float* __restrict__ xl,
                                const float* __restrict__ logits,
                                const float* __restrict__ conv_b, const float* __restrict__ rm,
                                const float* __restrict__ rv, const float* __restrict__ gg,
                                const float* __restrict__ gb, float* __restrict__ h,
                                int add_res) {
    int warp = threadIdx.x >> 5, lane = threadIdx.x & 31;
    int n = blockIdx.x * 8 + warp;
    if (n >= N_NODES) return;
    int beg = rowoff[n], end = rowoff[n + 1];
    int hh = lane >> 2, q = lane & 3;

    float mx = -1e30f;
    for (int j = beg + q; j < end; j += 4)
        mx = fmaxf(mx, logits[(size_t)perm[j] * HEADS + hh]);
    mx = fmaxf(mx, __shfl_xor_sync(0xffffffffu, mx, 1));
    mx = fmaxf(mx, __shfl_xor_sync(0xffffffffu, mx, 2));

    float den = 0.f;
    for (int j = beg + q; j < end; j += 4)
        den += __expf(logits[(size_t)perm[j] * HEADS + hh] - mx);
    den += __shfl_xor_sync(0xffffffffu, den, 1);
    den += __shfl_xor_sync(0xffffffffu, den, 2);
    float inv = 1.0f / (den + 1e-16f);

    float acc[8] = {0.f, 0.f, 0.f, 0.f, 0.f, 0.f, 0.f, 0.f};
    for (int j = beg; j < end; j++) {
        int e = perm[j];
        int sv = src[e];
        float w = __expf(logits[(size_t)e * HEADS + hh] - mx) * inv;
        const float4* p = (const float4*)(xl + (size_t)sv * HID + lane * 8);
        float4 v0 = p[0], v1 = p[1];
        acc[0] += w * v0.x; acc[1] += w * v0.y; acc[2] += w * v0.z; acc[3] += w * v0.w;
        acc[4] += w * v1.x; acc[5] += w * v1.y; acc[6] += w * v1.z; acc[7] += w * v1.w;
    }

    int cbase = lane * 8;
#pragma unroll
    for (int k = 0; k < 8; k++) {
        int c = cbase + k;
        float v = acc[k] + conv_b[c];
        v = (v - rm[c]) * rsqrtf(rv[c] + 1e-5f) * gg[c] + gb[c];
        v = (v >= 0.f) ? v : 0.01f * v;
        if (add_res) v += h[(size_t)n * HID + c];
        h[(size_t)n * HID + c] = v;
    }
}

// ---------------- final projection: [N,128] @ [128,1] ----------------
__global__ void out2_kernel(const float* __restrict__ mlp, const float* __restrict__ W2,
                            const float* __restrict__ b2, float* __restrict__ out) {
    int warp = threadIdx.x >> 5, lane = threadIdx.x & 31;
    int n = blockIdx.x * 8 + warp;
    if (n >= N_NODES) return;
    float4 m = *(const float4*)(mlp + (size_t)n * 128 + lane * 4);
    float4 w = *(const float4*)(W2 + lane * 4);
    float s = m.x * w.x + m.y * w.y + m.z * w.z + m.w * w.w;
#pragma unroll
    for (int off = 16; off; off >>= 1) s += __shfl_xor_sync(0xffffffffu, s, off);
    if (lane == 0) out[n] = s + b2[0];
}

// ---------------- launcher ----------------
static float* sym_f(const void* symbol) {
    void* p = nullptr;
    cudaGetSymbolAddress(&p, symbol);
    return (float*)p;
}
static int* sym_i(const void* symbol) {
    void* p = nullptr;
    cudaGetSymbolAddress(&p, symbol);
    return (int*)p;
}

extern "C" void kernel_launch(void* const* d_in, const int* in_sizes, int n_in,
                              void* d_out, int out_size) {
    const float* x        = (const float*)d_in[0];
    const int*   ei       = (const int*)  d_in[1];
    const float* edge_attr= (const float*)d_in[2];
    const float* node_W   = (const float*)d_in[3];
    const float* node_b   = (const float*)d_in[4];
    const float* edge_W   = (const float*)d_in[5];
    const float* edge_b   = (const float*)d_in[6];
    const float* Wl       = (const float*)d_in[7];
    const float* bl       = (const float*)d_in[8];
    const float* Wr       = (const float*)d_in[9];
    const float* br       = (const float*)d_in[10];
    const float* We       = (const float*)d_in[11];
    const float* att      = (const float*)d_in[12];
    const float* conv_b   = (const float*)d_in[13];
    const float* Weu      = (const float*)d_in[14];
    const float* beu      = (const float*)d_in[15];
    const float* bn_g     = (const float*)d_in[16];
    const float* bn_b     = (const float*)d_in[17];
    const float* bn_rm    = (const float*)d_in[18];
    const float* bn_rv    = (const float*)d_in[19];
    const float* out_W1   = (const float*)d_in[20];
    const float* out_b1   = (const float*)d_in[21];
    const float* out_W2   = (const float*)d_in[22];
    const float* out_b2   = (const float*)d_in[23];
    float* out = (float*)d_out;

    float* h   = sym_f(g_h);
    float* xl  = sym_f(g_xl);
    float* xr  = sym_f(g_xr);
    float* ea  = sym_f(g_ea);
    float* eb  = sym_f(g_eb);
    float* ep  = sym_f(g_ep);
    float* lg  = sym_f(g_log);
    float* mlp = sym_f(g_mlp);
    int* deg    = sym_i(g_deg);
    int* rowoff = sym_i(g_rowoff);
    int* cursor = sym_i(g_cursor);
    int* perm   = sym_i(g_perm);

    const int* src = ei;
    const int* dst = ei + E_EDGES;

    // CSR build (per launch; deterministic output)
    zero_int_kernel<<<(N_NODES + 255) / 256, 256>>>(deg, N_NODES);
    count_kernel<<<(E_EDGES + 255) / 256, 256>>>(dst, deg);
    scan_kernel<<<1, 1024>>>(deg, rowoff, cursor);
    scatter_kernel<<<(E_EDGES + 255) / 256, 256>>>(dst, cursor, perm);

    // input projections
    node_in_kernel<<<(N_NODES * HID + 255) / 256, 256>>>(x, node_W, node_b, h);
    edge_in_kernel<<<(int)(((size_t)E_EDGES * HID + 255) / 256), 256>>>(edge_attr, edge_W, edge_b, ea);

    float* pa = ea;
    float* pb = eb;

    dim3 gN((HID + GBN - 1) / GBN, (N_NODES + GBM - 1) / GBM);   // (2, 235)
    dim3 gE((HID + GBN - 1) / GBN, (E_EDGES + GBM - 1) / GBM);   // (2, 3750)

    for (int i = 0; i < NLAYERS; i++) {
        const float* Wl_i  = Wl  + (size_t)i * HID * HID;
        const float* Wr_i  = Wr  + (size_t)i * HID * HID;
        const float* We_i  = We  + (size_t)i * HID * HID;
        const float* Weu_i = Weu + (size_t)i * HID * HID;
        const float* bl_i  = bl  + i * HID;
        const float* br_i  = br  + i * HID;
        const float* beu_i = beu + i * HID;
        const float* att_i = att + i * HEADS * OUTC;

        gemm_kernel<<<gN, 256>>>(h, Wl_i, bl_i, xl, N_NODES, HID, HID, 0);
        gemm_kernel<<<gN, 256>>>(h, Wr_i, br_i, xr, N_NODES, HID, HID, 0);
        gemm_kernel<<<gE, 256>>>(pa, We_i, nullptr, ep, E_EDGES, HID, HID, 0);

        logits_kernel<<<(E_EDGES + 7) / 8, 256>>>(src, dst, xl, xr, ep, att_i, lg);
        node_agg_kernel<<<(N_NODES + 7) / 8, 256>>>(rowoff, perm, src, xl, lg,
                                                    conv_b + i * HID, bn_rm + i * HID,
                                                    bn_rv + i * HID, bn_g + i * HID,
                                                    bn_b + i * HID, h, (i >= 1) ? 1 : 0);

        gemm_kernel<<<gE, 256>>>(pa, Weu_i, beu_i, pb, E_EDGES, HID, HID, 0);
        float* t = pa; pa = pb; pb = t;
    }

    // output MLP
    dim3 gO(1, (N_NODES + GBM - 1) / GBM);
    gemm_kernel<<<gO, 256>>>(h, out_W1, out_b1, mlp, N_NODES, HID, 128, 1);
    out2_kernel<<<(N_NODES + 7) / 8, 256>>>(mlp, out_W2, out_b2, out);
}

// round 3
// speedup vs baseline: 2.9182x; 2.9182x over previous
#include <cuda_runtime.h>
#include <cuda_bf16.h>
#include <cstddef>
#include <cstdint>

#define N_NODES 30000
#define E_EDGES 480000
#define HID 256
#define HEADS 8
#define OUTC 32
#define NLAYERS 6
#define NODE_IN 13
#define EDGE_IN 10

// ---------------- static device scratch (no allocations allowed) ----------------
__device__ float g_h   [N_NODES * HID];
__device__ float g_xl  [N_NODES * HID];
__device__ float g_xr  [N_NODES * HID];
__device__ float g_ea  [(size_t)E_EDGES * HID];
__device__ float g_eb  [(size_t)E_EDGES * HID];
__device__ float g_ep  [(size_t)E_EDGES * HID];
__device__ float g_log [(size_t)E_EDGES * HEADS];
__device__ float g_mlp [N_NODES * 128];
__device__ int   g_deg [N_NODES];
__device__ int   g_rowoff[N_NODES + 1];
__device__ int   g_cursor[N_NODES];
__device__ int   g_perm[E_EDGES];

// ---------------- CSR build ----------------
__global__ void zero_int_kernel(int* p, int n) {
    int i = blockIdx.x * blockDim.x + threadIdx.x;
    if (i < n) p[i] = 0;
}

__global__ void count_kernel(const int* __restrict__ dst, int* __restrict__ deg) {
    int e = blockIdx.x * blockDim.x + threadIdx.x;
    if (e < E_EDGES) atomicAdd(&deg[dst[e]], 1);
}

__global__ void scan_kernel(const int* __restrict__ deg, int* __restrict__ rowoff,
                            int* __restrict__ cursor) {
    __shared__ int s[1024];
    int tid = threadIdx.x;
    const int CH = (N_NODES + 1023) / 1024;  // 30
    int base = tid * CH;
    int sum = 0;
    for (int i = 0; i < CH; i++) {
        int idx = base + i;
        if (idx < N_NODES) sum += deg[idx];
    }
    s[tid] = sum;
    __syncthreads();
    for (int off = 1; off < 1024; off <<= 1) {
        int v = (tid >= off) ? s[tid - off] : 0;
        __syncthreads();
        s[tid] += v;
        __syncthreads();
    }
    int run = s[tid] - sum;  // exclusive prefix
    for (int i = 0; i < CH; i++) {
        int idx = base + i;
        if (idx < N_NODES) {
            rowoff[idx] = run;
            cursor[idx] = run;
            run += deg[idx];
        }
    }
    if (tid == 1023) rowoff[N_NODES] = run;
}

__global__ void scatter_kernel(const int* __restrict__ dst, int* __restrict__ cursor,
                               int* __restrict__ perm) {
    int e = blockIdx.x * blockDim.x + threadIdx.x;
    if (e < E_EDGES) {
        int p = atomicAdd(&cursor[dst[e]], 1);
        perm[p] = e;
    }
}

// ---------------- input projections (small K) ----------------
__global__ void node_in_kernel(const float* __restrict__ x, const float* __restrict__ W,
                               const float* __restrict__ b, float* __restrict__ h) {
    int idx = blockIdx.x * blockDim.x + threadIdx.x;
    if (idx >= N_NODES * HID) return;
    int r = idx >> 8, c = idx & 255;
    float s = b[c];
#pragma unroll
    for (int k = 0; k < NODE_IN; k++) s += x[r * NODE_IN + k] * W[k * HID + c];
    h[idx] = s;
}

__global__ void edge_in_kernel(const float* __restrict__ ea_in, const float* __restrict__ W,
                               const float* __restrict__ b, float* __restrict__ ea) {
    size_t idx = (size_t)blockIdx.x * blockDim.x + threadIdx.x;
    if (idx >= (size_t)E_EDGES * HID) return;
    size_t r = idx >> 8;
    int c = (int)(idx & 255);
    float s = b[c];
#pragma unroll
    for (int k = 0; k < EDGE_IN; k++) s += ea_in[r * EDGE_IN + k] * W[k * HID + c];
    ea[idx] = s;
}

// ---------------- TF32 tensor-core GEMM ----------------
// C[M,Nc] = A[M,K] @ B[K,Nc] (+bias) (+leaky). Block 128x128x32, 8 warps (4x2),
// warp tile 32x64 via mma.m16n8k8.tf32. K must be a multiple of 32 (K=256 here).
#define BM 128
#define BN 128
#define BK 32
#define AS_STRIDE 36   // padded: conflict-free frag loads, keeps 16B alignment
#define BS_STRIDE 136

__device__ __forceinline__ uint32_t f2tf(float f) {
    uint32_t u;
    asm("cvt.rna.tf32.f32 %0, %1;" : "=r"(u) : "f"(f));
    return u;
}

__device__ __forceinline__ void mma_tf32(float* c, const uint32_t* a, uint32_t b0, uint32_t b1) {
    asm("mma.sync.aligned.m16n8k8.row.col.f32.tf32.tf32.f32 "
        "{%0,%1,%2,%3},{%4,%5,%6,%7},{%8,%9},{%0,%1,%2,%3};"
        : "+f"(c[0]), "+f"(c[1]), "+f"(c[2]), "+f"(c[3])
        : "r"(a[0]), "r"(a[1]), "r"(a[2]), "r"(a[3]), "r"(b0), "r"(b1));
}

__global__ __launch_bounds__(256, 2)
void gemm_tf32_kernel(const float* __restrict__ A, const float* __restrict__ B,
                      const float* __restrict__ bias, float* __restrict__ C,
                      int M, int K, int Nc, int act) {
    __shared__ uint32_t As[BM * AS_STRIDE];
    __shared__ uint32_t Bs[BK * BS_STRIDE];

    int tid = threadIdx.x;
    int lane = tid & 31, warp = tid >> 5;
    int warpM = warp & 3, warpN = warp >> 2;          // 4 x 2 warps
    int rowBase = blockIdx.y * BM;
    int colBase = blockIdx.x * BN;
    int gid = lane >> 2;                               // group id (0..7)
    int tig = lane & 3;                                // thread in group (0..3)

    float acc[2][8][4];
#pragma unroll
    for (int mt = 0; mt < 2; mt++)
#pragma unroll
        for (int nt = 0; nt < 8; nt++)
#pragma unroll
            for (int i = 0; i < 4; i++) acc[mt][nt][i] = 0.f;

    for (int k0 = 0; k0 < K; k0 += BK) {
        // stage A tile [128 x 32] (cvt to tf32 on the way in)
#pragma unroll
        for (int i = 0; i < 4; i++) {
            int idx = tid + i * 256;
            int row = idx >> 3, q = idx & 7;
            int gr = rowBase + row;
            float4 v = make_float4(0.f, 0.f, 0.f, 0.f);
            if (gr < M) v = *(const float4*)(A + (size_t)gr * K + k0 + q * 4);
            uint32_t* p = &As[row * AS_STRIDE + q * 4];
            p[0] = f2tf(v.x); p[1] = f2tf(v.y); p[2] = f2tf(v.z); p[3] = f2tf(v.w);
        }
        // stage B tile [32 x 128]
#pragma unroll
        for (int i = 0; i < 4; i++) {
            int idx = tid + i * 256;
            int row = idx >> 5, q = idx & 31;
            float4 v = *(const float4*)(B + (size_t)(k0 + row) * Nc + colBase + q * 4);
            uint32_t* p = &Bs[row * BS_STRIDE + q * 4];
            p[0] = f2tf(v.x); p[1] = f2tf(v.y); p[2] = f2tf(v.z); p[3] = f2tf(v.w);
        }
        __syncthreads();

#pragma unroll
        for (int kk = 0; kk < 4; kk++) {
            int ko = kk * 8;
            uint32_t af[2][4];
#pragma unroll
            for (int mt = 0; mt < 2; mt++) {
                int r = warpM * 32 + mt * 16 + gid;
                af[mt][0] = As[r * AS_STRIDE + ko + tig];
                af[mt][1] = As[(r + 8) * AS_STRIDE + ko + tig];
                af[mt][2] = As[r * AS_STRIDE + ko + tig + 4];
                af[mt][3] = As[(r + 8) * AS_STRIDE + ko + tig + 4];
            }
#pragma unroll
            for (int nt = 0; nt < 8; nt++) {
                int n = warpN * 64 + nt * 8 + gid;
                uint32_t b0 = Bs[(ko + tig) * BS_STRIDE + n];
                uint32_t b1 = Bs[(ko + tig + 4) * BS_STRIDE + n];
                mma_tf32(acc[0][nt], af[0], b0, b1);
                mma_tf32(acc[1][nt], af[1], b0, b1);
            }
        }
        __syncthreads();
    }

    // epilogue
#pragma unroll
    for (int mt = 0; mt < 2; mt++) {
        int r0 = rowBase + warpM * 32 + mt * 16 + gid;
        int r1 = r0 + 8;
#pragma unroll
        for (int nt = 0; nt < 8; nt++) {
            int c0 = colBase + warpN * 64 + nt * 8 + tig * 2;
            float v0 = acc[mt][nt][0], v1 = acc[mt][nt][1];
            float v2 = acc[mt][nt][2], v3 = acc[mt][nt][3];
            if (bias) {
                float b0 = bias[c0], b1 = bias[c0 + 1];
                v0 += b0; v1 += b1; v2 += b0; v3 += b1;
            }
            if (act) {
                v0 = (v0 >= 0.f) ? v0 : 0.01f * v0;
                v1 = (v1 >= 0.f) ? v1 : 0.01f * v1;
                v2 = (v2 >= 0.f) ? v2 : 0.01f * v2;
                v3 = (v3 >= 0.f) ? v3 : 0.01f * v3;
            }
            if (r0 < M) *(float2*)(C + (size_t)r0 * Nc + c0) = make_float2(v0, v1);
            if (r1 < M) *(float2*)(C + (size_t)r1 * Nc + c0) = make_float2(v2, v3);
        }
    }
}

// ---------------- attention logits: one warp per edge ----------------
__global__ void logits_kernel(const int* __restrict__ src, const int* __restrict__ dst,
                              const float* __restrict__ xl, const float* __restrict__ xr,
                              const float* __restrict__ ep, const float* __restrict__ att_l,
                              float* __restrict__ logits) {
    __shared__ float satt[HID];
    int tid = threadIdx.x;
    satt[tid] = att_l[tid];
    __syncthreads();
    int warp = tid >> 5, lane = tid & 31;
    int e = blockIdx.x * 8 + warp;
    if (e >= E_EDGES) return;
    int s = src[e], d = dst[e];
    const float4* pl = (const float4*)(xl + (size_t)s * HID + lane * 8);
    const float4* pr = (const float4*)(xr + (size_t)d * HID + lane * 8);
    const float4* pe = (const float4*)(ep + (size_t)e * HID + lane * 8);
    float4 l0 = pl[0], l1 = pl[1];
    float4 r0 = pr[0], r1 = pr[1];
    float4 e0 = pe[0], e1 = pe[1];
    float vv[8] = {l0.x + r0.x + e0.x, l0.y + r0.y + e0.y, l0.z + r0.z + e0.z, l0.w + r0.w + e0.w,
                   l1.x + r1.x + e1.x, l1.y + r1.y + e1.y, l1.z + r1.z + e1.z, l1.w + r1.w + e1.w};
    float sum = 0.f;
#pragma unroll
    for (int j = 0; j < 8; j++) {
        float v = vv[j];
        v = (v >= 0.f) ? v : 0.2f * v;           // leaky 0.2
        sum += v * satt[lane * 8 + j];
    }
    sum += __shfl_xor_sync(0xffffffffu, sum, 1);
    sum += __shfl_xor_sync(0xffffffffu, sum, 2);
    if ((lane & 3) == 0) logits[(size_t)e * HEADS + (lane >> 2)] = sum;
}

// ---------------- fused per-node: softmax + aggregate + bias + BN + leaky + residual ----------------
__global__ void node_agg_kernel(const int* __restrict__ rowoff, const int* __restrict__ perm,
                                const int* __restrict__ src, const float* __restrict__ xl,
                                const float* __restrict__ logits,
                                const float* __restrict__ conv_b, const float* __restrict__ rm,
                                const float* __restrict__ rv, const float* __restrict__ gg,
                                const float* __restrict__ gb, float* __restrict__ h,
                                int add_res) {
    int warp = threadIdx.x >> 5, lane = threadIdx.x & 31;
    int n = blockIdx.x * 8 + warp;
    if (n >= N_NODES) return;
    int beg = rowoff[n], end = rowoff[n + 1];
    int hh = lane >> 2, q = lane & 3;

    float mx = -1e30f;
    for (int j = beg + q; j < end; j += 4)
        mx = fmaxf(mx, logits[(size_t)perm[j] * HEADS + hh]);
    mx = fmaxf(mx, __shfl_xor_sync(0xffffffffu, mx, 1));
    mx = fmaxf(mx, __shfl_xor_sync(0xffffffffu, mx, 2));

    float den = 0.f;
    for (int j = beg + q; j < end; j += 4)
        den += __expf(logits[(size_t)perm[j] * HEADS + hh] - mx);
    den += __shfl_xor_sync(0xffffffffu, den, 1);
    den += __shfl_xor_sync(0xffffffffu, den, 2);
    float inv = 1.0f / (den + 1e-16f);

    float acc[8] = {0.f, 0.f, 0.f, 0.f, 0.f, 0.f, 0.f, 0.f};
    for (int j = beg; j < end; j++) {
        int e = perm[j];
        int sv = src[e];
        float w = __expf(logits[(size_t)e * HEADS + hh] - mx) * inv;
        const float4* p = (const float4*)(xl + (size_t)sv * HID + lane * 8);
        float4 v0 = p[0], v1 = p[1];
        acc[0] += w * v0.x; acc[1] += w * v0.y; acc[2] += w * v0.z; acc[3] += w * v0.w;
        acc[4] += w * v1.x; acc[5] += w * v1.y; acc[6] += w * v1.z; acc[7] += w * v1.w;
    }

    int cbase = lane * 8;
#pragma unroll
    for (int k = 0; k < 8; k++) {
        int c = cbase + k;
        float v = acc[k] + conv_b[c];
        v = (v - rm[c]) * rsqrtf(rv[c] + 1e-5f) * gg[c] + gb[c];
        v = (v >= 0.f) ? v : 0.01f * v;
        if (add_res) v += h[(size_t)n * HID + c];
        h[(size_t)n * HID + c] = v;
    }
}

// ---------------- final projection: [N,128] @ [128,1] ----------------
__global__ void out2_kernel(const float* __restrict__ mlp, const float* __restrict__ W2,
                            const float* __restrict__ b2, float* __restrict__ out) {
    int warp = threadIdx.x >> 5, lane = threadIdx.x & 31;
    int n = blockIdx.x * 8 + warp;
    if (n >= N_NODES) return;
    float4 m = *(const float4*)(mlp + (size_t)n * 128 + lane * 4);
    float4 w = *(const float4*)(W2 + lane * 4);
    float s = m.x * w.x + m.y * w.y + m.z * w.z + m.w * w.w;
#pragma unroll
    for (int off = 16; off; off >>= 1) s += __shfl_xor_sync(0xffffffffu, s, off);
    if (lane == 0) out[n] = s + b2[0];
}

// ---------------- launcher ----------------
static float* sym_f(const void* symbol) {
    void* p = nullptr;
    cudaGetSymbolAddress(&p, symbol);
    return (float*)p;
}
static int* sym_i(const void* symbol) {
    void* p = nullptr;
    cudaGetSymbolAddress(&p, symbol);
    return (int*)p;
}

extern "C" void kernel_launch(void* const* d_in, const int* in_sizes, int n_in,
                              void* d_out, int out_size) {
    const float* x        = (const float*)d_in[0];
    const int*   ei       = (const int*)  d_in[1];
    const float* edge_attr= (const float*)d_in[2];
    const float* node_W   = (const float*)d_in[3];
    const float* node_b   = (const float*)d_in[4];
    const float* edge_W   = (const float*)d_in[5];
    const float* edge_b   = (const float*)d_in[6];
    const float* Wl       = (const float*)d_in[7];
    const float* bl       = (const float*)d_in[8];
    const float* Wr       = (const float*)d_in[9];
    const float* br       = (const float*)d_in[10];
    const float* We       = (const float*)d_in[11];
    const float* att      = (const float*)d_in[12];
    const float* conv_b   = (const float*)d_in[13];
    const float* Weu      = (const float*)d_in[14];
    const float* beu      = (const float*)d_in[15];
    const float* bn_g     = (const float*)d_in[16];
    const float* bn_b     = (const float*)d_in[17];
    const float* bn_rm    = (const float*)d_in[18];
    const float* bn_rv    = (const float*)d_in[19];
    const float* out_W1   = (const float*)d_in[20];
    const float* out_b1   = (const float*)d_in[21];
    const float* out_W2   = (const float*)d_in[22];
    const float* out_b2   = (const float*)d_in[23];
    float* out = (float*)d_out;

    float* h   = sym_f(g_h);
    float* xl  = sym_f(g_xl);
    float* xr  = sym_f(g_xr);
    float* ea  = sym_f(g_ea);
    float* eb  = sym_f(g_eb);
    float* ep  = sym_f(g_ep);
    float* lg  = sym_f(g_log);
    float* mlp = sym_f(g_mlp);
    int* deg    = sym_i(g_deg);
    int* rowoff = sym_i(g_rowoff);
    int* cursor = sym_i(g_cursor);
    int* perm   = sym_i(g_perm);

    const int* src = ei;
    const int* dst = ei + E_EDGES;

    // CSR build (per launch; deterministic output)
    zero_int_kernel<<<(N_NODES + 255) / 256, 256>>>(deg, N_NODES);
    count_kernel<<<(E_EDGES + 255) / 256, 256>>>(dst, deg);
    scan_kernel<<<1, 1024>>>(deg, rowoff, cursor);
    scatter_kernel<<<(E_EDGES + 255) / 256, 256>>>(dst, cursor, perm);

    // input projections
    node_in_kernel<<<(N_NODES * HID + 255) / 256, 256>>>(x, node_W, node_b, h);
    edge_in_kernel<<<(int)(((size_t)E_EDGES * HID + 255) / 256), 256>>>(edge_attr, edge_W, edge_b, ea);

    float* pa = ea;
    float* pb = eb;

    dim3 gN((HID + BN - 1) / BN, (N_NODES + BM - 1) / BM);   // (2, 235)
    dim3 gE((HID + BN - 1) / BN, (E_EDGES + BM - 1) / BM);   // (2, 3750)

    for (int i = 0; i < NLAYERS; i++) {
        const float* Wl_i  = Wl  + (size_t)i * HID * HID;
        const float* Wr_i  = Wr  + (size_t)i * HID * HID;
        const float* We_i  = We  + (size_t)i * HID * HID;
        const float* Weu_i = Weu + (size_t)i * HID * HID;
        const float* bl_i  = bl  + i * HID;
        const float* br_i  = br  + i * HID;
        const float* beu_i = beu + i * HID;
        const float* att_i = att + i * HEADS * OUTC;

        gemm_tf32_kernel<<<gN, 256>>>(h, Wl_i, bl_i, xl, N_NODES, HID, HID, 0);
        gemm_tf32_kernel<<<gN, 256>>>(h, Wr_i, br_i, xr, N_NODES, HID, HID, 0);
        gemm_tf32_kernel<<<gE, 256>>>(pa, We_i, nullptr, ep, E_EDGES, HID, HID, 0);

        logits_kernel<<<(E_EDGES + 7) / 8, 256>>>(src, dst, xl, xr, ep, att_i, lg);
        node_agg_kernel<<<(N_NODES + 7) / 8, 256>>>(rowoff, perm, src, xl, lg,
                                                    conv_b + i * HID, bn_rm + i * HID,
                                                    bn_rv + i * HID, bn_g + i * HID,
                                                    bn_b + i * HID, h, (i >= 1) ? 1 : 0);

        gemm_tf32_kernel<<<gE, 256>>>(pa, Weu_i, beu_i, pb, E_EDGES, HID, HID, 0);
        float* t = pa; pa = pb; pb = t;
    }

    // output MLP
    dim3 gO(1, (N_NODES + BM - 1) / BM);
    gemm_tf32_kernel<<<gO, 256>>>(h, out_W1, out_b1, mlp, N_NODES, HID, 128, 1);
    out2_kernel<<<(N_NODES + 7) / 8, 256>>>(mlp, out_W2, out_b2, out);
}

// round 5
// speedup vs baseline: 5.6682x; 1.9424x over previous
#include <cuda_runtime.h>
#include <cuda_bf16.h>
#include <cstddef>
#include <cstdint>

#define N_NODES 30000
#define E_EDGES 480000
#define HID 256
#define HEADS 8
#define NLAYERS 6
#define NODE_IN 13
#define EDGE_IN 10

// ---------------- static device scratch (no allocations allowed) ----------------
__device__ float g_h   [N_NODES * HID];
__device__ float g_xl  [N_NODES * HID];
__device__ float g_xr  [N_NODES * HID];
__device__ float g_log [(size_t)E_EDGES * HEADS];
__device__ float g_mlp [N_NODES * 128];
__device__ float g_V   [NLAYERS * 11 * HID];   // rows 0..9: edge_attr coeffs; row 10: const
__device__ int   g_deg [N_NODES];
__device__ int   g_rowoff[N_NODES + 1];
__device__ int   g_cursor[N_NODES];
__device__ int   g_perm[E_EDGES];

// ---------------- CSR build ----------------
__global__ void zero_int_kernel(int* p, int n) {
    int i = blockIdx.x * blockDim.x + threadIdx.x;
    if (i < n) p[i] = 0;
}

__global__ void count_kernel(const int* __restrict__ dst, int* __restrict__ deg) {
    int e = blockIdx.x * blockDim.x + threadIdx.x;
    if (e < E_EDGES) atomicAdd(&deg[dst[e]], 1);
}

__global__ void scan_kernel(const int* __restrict__ deg, int* __restrict__ rowoff,
                            int* __restrict__ cursor) {
    __shared__ int s[1024];
    int tid = threadIdx.x;
    const int CH = (N_NODES + 1023) / 1024;  // 30
    int base = tid * CH;
    int sum = 0;
    for (int i = 0; i < CH; i++) {
        int idx = base + i;
        if (idx < N_NODES) sum += deg[idx];
    }
    s[tid] = sum;
    __syncthreads();
    for (int off = 1; off < 1024; off <<= 1) {
        int v = (tid >= off) ? s[tid - off] : 0;
        __syncthreads();
        s[tid] += v;
        __syncthreads();
    }
    int run = s[tid] - sum;  // exclusive prefix
    for (int i = 0; i < CH; i++) {
        int idx = base + i;
        if (idx < N_NODES) {
            rowoff[idx] = run;
            cursor[idx] = run;
            run += deg[idx];
        }
    }
    if (tid == 1023) rowoff[N_NODES] = run;
}

__global__ void scatter_kernel(const int* __restrict__ dst, int* __restrict__ cursor,
                               int* __restrict__ perm) {
    int e = blockIdx.x * blockDim.x + threadIdx.x;
    if (e < E_EDGES) {
        int p = atomicAdd(&cursor[dst[e]], 1);
        perm[p] = e;
    }
}

// ---------------- node input projection ----------------
__global__ void node_in_kernel(const float* __restrict__ x, const float* __restrict__ W,
                               const float* __restrict__ b, float* __restrict__ h) {
    int idx = blockIdx.x * blockDim.x + threadIdx.x;
    if (idx >= N_NODES * HID) return;
    int r = idx >> 8, c = idx & 255;
    float s = b[c];
#pragma unroll
    for (int k = 0; k < NODE_IN; k++) s += x[r * NODE_IN + k] * W[k * HID + c];
    h[idx] = s;
}

// ---------------- edge-chain collapse: V_l = Uaug_l @ We_l, Uaug_{l+1} = Uaug_l @ Weu_l (+beu) ----------------
// Uaug: rows 0..9 map edge_attr, row 10 is the constant term. One block, 256 threads.
__global__ void precompute_V_kernel(const float* __restrict__ edge_W, const float* __restrict__ edge_b,
                                    const float* __restrict__ We, const float* __restrict__ Weu,
                                    const float* __restrict__ beu, float* __restrict__ V) {
    __shared__ float U[11][HID];
    int c = threadIdx.x;  // 0..255
    for (int k = 0; k < EDGE_IN; k++) U[k][c] = edge_W[k * HID + c];
    U[10][c] = edge_b[c];
    __syncthreads();
    for (int l = 0; l < NLAYERS; l++) {
        const float* WeL  = We  + (size_t)l * HID * HID;
        const float* WeuL = Weu + (size_t)l * HID * HID;
        float accV[11], accU[11];
#pragma unroll
        for (int k = 0; k < 11; k++) { accV[k] = 0.f; accU[k] = 0.f; }
        for (int j = 0; j < HID; j++) {
            float we  = WeL [j * HID + c];
            float weu = WeuL[j * HID + c];
#pragma unroll
            for (int k = 0; k < 11; k++) {
                float u = U[k][j];
                accV[k] += u * we;
                accU[k] += u * weu;
            }
        }
        accU[10] += beu[l * HID + c];
#pragma unroll
        for (int k = 0; k < 11; k++) V[((size_t)l * 11 + k) * HID + c] = accV[k];
        __syncthreads();
#pragma unroll
        for (int k = 0; k < 11; k++) U[k][c] = accU[k];
        __syncthreads();
    }
}

// ---------------- 3xTF32 tensor-core GEMM (near-fp32 accuracy) ----------------
// C[M,Nc] = A[M,K] @ B[K,Nc] (+bias) (+leaky). Block 128x128x16, 8 warps (4x2),
// warp tile 32x64 via mma.m16n8k8.tf32. A/B split hi+lo; 3 mma per product.
#define BM 128
#define BN 128
#define BK 16
#define AS_STRIDE 20
#define BS_STRIDE 136

__device__ __forceinline__ uint32_t f2tf(float f) {
    uint32_t u;
    asm("cvt.rna.tf32.f32 %0, %1;" : "=r"(u) : "f"(f));
    return u;
}

__device__ __forceinline__ void mma_tf32(float* c, const uint32_t* a, uint32_t b0, uint32_t b1) {
    asm("mma.sync.aligned.m16n8k8.row.col.f32.tf32.tf32.f32 "
        "{%0,%1,%2,%3},{%4,%5,%6,%7},{%8,%9},{%0,%1,%2,%3};"
        : "+f"(c[0]), "+f"(c[1]), "+f"(c[2]), "+f"(c[3])
        : "r"(a[0]), "r"(a[1]), "r"(a[2]), "r"(a[3]), "r"(b0), "r"(b1));
}

__device__ __forceinline__ void split_tf(float f, uint32_t& hi, uint32_t& lo) {
    hi = f2tf(f);
    lo = f2tf(f - __uint_as_float(hi));
}

__global__ __launch_bounds__(256, 2)
void gemm_tf32x3_kernel(const float* __restrict__ A, const float* __restrict__ B,
                        const float* __restrict__ bias, float* __restrict__ C,
                        int M, int K, int Nc, int act) {
    __shared__ uint32_t AsH[BM * AS_STRIDE], AsL[BM * AS_STRIDE];
    __shared__ uint32_t BsH[BK * BS_STRIDE], BsL[BK * BS_STRIDE];

    int tid = threadIdx.x;
    int lane = tid & 31, warp = tid >> 5;
    int warpM = warp & 3, warpN = warp >> 2;  // 4 x 2
    int rowBase = blockIdx.y * BM;
    int colBase = blockIdx.x * BN;
    int gid = lane >> 2, tig = lane & 3;

    float acc[2][8][4];
#pragma unroll
    for (int mt = 0; mt < 2; mt++)
#pragma unroll
        for (int nt = 0; nt < 8; nt++)
#pragma unroll
            for (int i = 0; i < 4; i++) acc[mt][nt][i] = 0.f;

    for (int k0 = 0; k0 < K; k0 += BK) {
        // stage A [128 x 16]
#pragma unroll
        for (int i = 0; i < 2; i++) {
            int idx = tid + i * 256;
            int row = idx >> 2, q = idx & 3;
            int gr = rowBase + row;
            float4 v = make_float4(0.f, 0.f, 0.f, 0.f);
            if (gr < M) v = *(const float4*)(A + (size_t)gr * K + k0 + q * 4);
            uint32_t h0, l0, h1, l1, h2, l2, h3, l3;
            split_tf(v.x, h0, l0); split_tf(v.y, h1, l1);
            split_tf(v.z, h2, l2); split_tf(v.w, h3, l3);
            uint32_t* ph = &AsH[row * AS_STRIDE + q * 4];
            uint32_t* pl = &AsL[row * AS_STRIDE + q * 4];
            ph[0] = h0; ph[1] = h1; ph[2] = h2; ph[3] = h3;
            pl[0] = l0; pl[1] = l1; pl[2] = l2; pl[3] = l3;
        }
        // stage B [16 x 128]
#pragma unroll
        for (int i = 0; i < 2; i++) {
            int idx = tid + i * 256;
            int row = idx >> 5, q = idx & 31;
            float4 v = *(const float4*)(B + (size_t)(k0 + row) * Nc + colBase + q * 4);
            uint32_t h0, l0, h1, l1, h2, l2, h3, l3;
            split_tf(v.x, h0, l0); split_tf(v.y, h1, l1);
            split_tf(v.z, h2, l2); split_tf(v.w, h3, l3);
            uint32_t* ph = &BsH[row * BS_STRIDE + q * 4];
            uint32_t* pl = &BsL[row * BS_STRIDE + q * 4];
            ph[0] = h0; ph[1] = h1; ph[2] = h2; ph[3] = h3;
            pl[0] = l0; pl[1] = l1; pl[2] = l2; pl[3] = l3;
        }
        __syncthreads();

#pragma unroll
        for (int kk = 0; kk < 2; kk++) {
            int ko = kk * 8;
            uint32_t afh[2][4], afl[2][4];
#pragma unroll
            for (int mt = 0; mt < 2; mt++) {
                int r = warpM * 32 + mt * 16 + gid;
                afh[mt][0] = AsH[r * AS_STRIDE + ko + tig];
                afh[mt][1] = AsH[(r + 8) * AS_STRIDE + ko + tig];
                afh[mt][2] = AsH[r * AS_STRIDE + ko + tig + 4];
                afh[mt][3] = AsH[(r + 8) * AS_STRIDE + ko + tig + 4];
                afl[mt][0] = AsL[r * AS_STRIDE + ko + tig];
                afl[mt][1] = AsL[(r + 8) * AS_STRIDE + ko + tig];
                afl[mt][2] = AsL[r * AS_STRIDE + ko + tig + 4];
                afl[mt][3] = AsL[(r + 8) * AS_STRIDE + ko + tig + 4];
            }
#pragma unroll
            for (int nt = 0; nt < 8; nt++) {
                int n = warpN * 64 + nt * 8 + gid;
                uint32_t bh0 = BsH[(ko + tig) * BS_STRIDE + n];
                uint32_t bh1 = BsH[(ko + tig + 4) * BS_STRIDE + n];
                uint32_t bl0 = BsL[(ko + tig) * BS_STRIDE + n];
                uint32_t bl1 = BsL[(ko + tig + 4) * BS_STRIDE + n];
#pragma unroll
                for (int mt = 0; mt < 2; mt++) {
                    mma_tf32(acc[mt][nt], afh[mt], bh0, bh1);  // hi*hi
                    mma_tf32(acc[mt][nt], afh[mt], bl0, bl1);  // hi*lo
                    mma_tf32(acc[mt][nt], afl[mt], bh0, bh1);  // lo*hi
                }
            }
        }
        __syncthreads();
    }

#pragma unroll
    for (int mt = 0; mt < 2; mt++) {
        int r0 = rowBase + warpM * 32 + mt * 16 + gid;
        int r1 = r0 + 8;
#pragma unroll
        for (int nt = 0; nt < 8; nt++) {
            int c0 = colBase + warpN * 64 + nt * 8 + tig * 2;
            float v0 = acc[mt][nt][0], v1 = acc[mt][nt][1];
            float v2 = acc[mt][nt][2], v3 = acc[mt][nt][3];
            if (bias) {
                float b0 = bias[c0], b1 = bias[c0 + 1];
                v0 += b0; v1 += b1; v2 += b0; v3 += b1;
            }
            if (act) {
                v0 = (v0 >= 0.f) ? v0 : 0.01f * v0;
                v1 = (v1 >= 0.f) ? v1 : 0.01f * v1;
                v2 = (v2 >= 0.f) ? v2 : 0.01f * v2;
                v3 = (v3 >= 0.f) ? v3 : 0.01f * v3;
            }
            if (r0 < M) *(float2*)(C + (size_t)r0 * Nc + c0) = make_float2(v0, v1);
            if (r1 < M) *(float2*)(C + (size_t)r1 * Nc + c0) = make_float2(v2, v3);
        }
    }
}

// ---------------- fused attention: logits + softmax + aggregate + BN + leaky + residual ----------------
// One warp per destination node. ep reconstructed on the fly from V (11x256 in smem).
__global__ __launch_bounds__(256)
void attn_kernel(const int* __restrict__ rowoff, const int* __restrict__ perm,
                 const int* __restrict__ src, const float* __restrict__ xl,
                 const float* __restrict__ xr, const float* __restrict__ eattr,
                 const float* __restrict__ V_l, const float* __restrict__ att_l,
                 const float* __restrict__ conv_b, const float* __restrict__ rm,
                 const float* __restrict__ rv, const float* __restrict__ gg,
                 const float* __restrict__ gb, float* __restrict__ h,
                 float* __restrict__ logits, int add_res) {
    __shared__ float sV[11 * HID];
    __shared__ float satt[HID];
    int tid = threadIdx.x;
    satt[tid] = att_l[tid];
    for (int i = tid; i < 11 * HID; i += 256) sV[i] = V_l[i];
    __syncthreads();

    int warp = tid >> 5, lane = tid & 31;
    int n = blockIdx.x * 8 + warp;
    if (n >= N_NODES) return;
    int beg = rowoff[n], end = rowoff[n + 1];
    int hh = lane >> 2, tig = lane & 3;
    int cb = lane * 8;

    float4 xr0 = *(const float4*)(xr + (size_t)n * HID + cb);
    float4 xr1 = *(const float4*)(xr + (size_t)n * HID + cb + 4);
    float4 at0 = *(const float4*)&satt[cb];
    float4 at1 = *(const float4*)&satt[cb + 4];
    float4 vc0 = *(const float4*)&sV[10 * HID + cb];      // constant term
    float4 vc1 = *(const float4*)&sV[10 * HID + cb + 4];

    // pass 1: logits + max
    float mx = -1e30f;
    for (int j = beg; j < end; j++) {
        int e = perm[j];
        int s = src[e];
        const float* ept = eattr + (size_t)e * EDGE_IN;
        const float4* pl = (const float4*)(xl + (size_t)s * HID + cb);
        float4 l0 = pl[0], l1 = pl[1];
        float ep[8] = {vc0.x, vc0.y, vc0.z, vc0.w, vc1.x, vc1.y, vc1.z, vc1.w};
#pragma unroll
        for (int k = 0; k < EDGE_IN; k++) {
            float ev = __ldg(ept + k);
            const float4* pv = (const float4*)&sV[k * HID + cb];
            float4 w0 = pv[0], w1 = pv[1];
            ep[0] += ev * w0.x; ep[1] += ev * w0.y; ep[2] += ev * w0.z; ep[3] += ev * w0.w;
            ep[4] += ev * w1.x; ep[5] += ev * w1.y; ep[6] += ev * w1.z; ep[7] += ev * w1.w;
        }
        float m0 = l0.x + xr0.x + ep[0];
        float m1 = l0.y + xr0.y + ep[1];
        float m2 = l0.z + xr0.z + ep[2];
        float m3 = l0.w + xr0.w + ep[3];
        float m4 = l1.x + xr1.x + ep[4];
        float m5 = l1.y + xr1.y + ep[5];
        float m6 = l1.z + xr1.z + ep[6];
        float m7 = l1.w + xr1.w + ep[7];
        m0 = (m0 >= 0.f) ? m0 : 0.2f * m0;  m1 = (m1 >= 0.f) ? m1 : 0.2f * m1;
        m2 = (m2 >= 0.f) ? m2 : 0.2f * m2;  m3 = (m3 >= 0.f) ? m3 : 0.2f * m3;
        m4 = (m4 >= 0.f) ? m4 : 0.2f * m4;  m5 = (m5 >= 0.f) ? m5 : 0.2f * m5;
        m6 = (m6 >= 0.f) ? m6 : 0.2f * m6;  m7 = (m7 >= 0.f) ? m7 : 0.2f * m7;
        float sum = m0 * at0.x + m1 * at0.y + m2 * at0.z + m3 * at0.w
                  + m4 * at1.x + m5 * at1.y + m6 * at1.z + m7 * at1.w;
        sum += __shfl_xor_sync(0xffffffffu, sum, 1);
        sum += __shfl_xor_sync(0xffffffffu, sum, 2);
        if (tig == 0) logits[(size_t)e * HEADS + hh] = sum;
        mx = fmaxf(mx, sum);
    }
    __syncwarp();

    // pass 2: denominator
    float den = 0.f;
    for (int j = beg + tig; j < end; j += 4)
        den += __expf(logits[(size_t)perm[j] * HEADS + hh] - mx);
    den += __shfl_xor_sync(0xffffffffu, den, 1);
    den += __shfl_xor_sync(0xffffffffu, den, 2);
    float inv = 1.0f / (den + 1e-16f);

    // pass 3: weighted aggregation
    float acc[8] = {0.f, 0.f, 0.f, 0.f, 0.f, 0.f, 0.f, 0.f};
    for (int j = beg; j < end; j++) {
        int e = perm[j];
        int s = src[e];
        float w = __expf(logits[(size_t)e * HEADS + hh] - mx) * inv;
        const float4* p = (const float4*)(xl + (size_t)s * HID + cb);
        float4 v0 = p[0], v1 = p[1];
        acc[0] += w * v0.x; acc[1] += w * v0.y; acc[2] += w * v0.z; acc[3] += w * v0.w;
        acc[4] += w * v1.x; acc[5] += w * v1.y; acc[6] += w * v1.z; acc[7] += w * v1.w;
    }

    // epilogue: conv bias + BN + leaky + residual
#pragma unroll
    for (int k = 0; k < 8; k++) {
        int c = cb + k;
        float v = acc[k] + conv_b[c];
        v = (v - rm[c]) * rsqrtf(rv[c] + 1e-5f) * gg[c] + gb[c];
        v = (v >= 0.f) ? v : 0.01f * v;
        if (add_res) v += h[(size_t)n * HID + c];
        h[(size_t)n * HID + c] = v;
    }
}

// ---------------- final projection: [N,128] @ [128,1] ----------------
__global__ void out2_kernel(const float* __restrict__ mlp, const float* __restrict__ W2,
                            const float* __restrict__ b2, float* __restrict__ out) {
    int warp = threadIdx.x >> 5, lane = threadIdx.x & 31;
    int n = blockIdx.x * 8 + warp;
    if (n >= N_NODES) return;
    float4 m = *(const float4*)(mlp + (size_t)n * 128 + lane * 4);
    float4 w = *(const float4*)(W2 + lane * 4);
    float s = m.x * w.x + m.y * w.y + m.z * w.z + m.w * w.w;
#pragma unroll
    for (int off = 16; off; off >>= 1) s += __shfl_xor_sync(0xffffffffu, s, off);
    if (lane == 0) out[n] = s + b2[0];
}

// ---------------- launcher ----------------
static float* sym_f(const void* symbol) {
    void* p = nullptr;
    cudaGetSymbolAddress(&p, symbol);
    return (float*)p;
}
static int* sym_i(const void* symbol) {
    void* p = nullptr;
    cudaGetSymbolAddress(&p, symbol);
    return (int*)p;
}

extern "C" void kernel_launch(void* const* d_in, const int* in_sizes, int n_in,
                              void* d_out, int out_size) {
    const float* x        = (const float*)d_in[0];
    const int*   ei       = (const int*)  d_in[1];
    const float* edge_attr= (const float*)d_in[2];
    const float* node_W   = (const float*)d_in[3];
    const float* node_b   = (const float*)d_in[4];
    const float* edge_W   = (const float*)d_in[5];
    const float* edge_b   = (const float*)d_in[6];
    const float* Wl       = (const float*)d_in[7];
    const float* bl       = (const float*)d_in[8];
    const float* Wr       = (const float*)d_in[9];
    const float* br       = (const float*)d_in[10];
    const float* We       = (const float*)d_in[11];
    const float* att      = (const float*)d_in[12];
    const float* conv_b   = (const float*)d_in[13];
    const float* Weu      = (const float*)d_in[14];
    const float* beu      = (const float*)d_in[15];
    const float* bn_g     = (const float*)d_in[16];
    const float* bn_b     = (const float*)d_in[17];
    const float* bn_rm    = (const float*)d_in[18];
    const float* bn_rv    = (const float*)d_in[19];
    const float* out_W1   = (const float*)d_in[20];
    const float* out_b1   = (const float*)d_in[21];
    const float* out_W2   = (const float*)d_in[22];
    const float* out_b2   = (const float*)d_in[23];
    float* out = (float*)d_out;

    float* h   = sym_f(g_h);
    float* xl  = sym_f(g_xl);
    float* xr  = sym_f(g_xr);
    float* lg  = sym_f(g_log);
    float* mlp = sym_f(g_mlp);
    float* V   = sym_f(g_V);
    int* deg    = sym_i(g_deg);
    int* rowoff = sym_i(g_rowoff);
    int* cursor = sym_i(g_cursor);
    int* perm   = sym_i(g_perm);

    const int* src = ei;
    const int* dst = ei + E_EDGES;

    // CSR build
    zero_int_kernel<<<(N_NODES + 255) / 256, 256>>>(deg, N_NODES);
    count_kernel<<<(E_EDGES + 255) / 256, 256>>>(dst, deg);
    scan_kernel<<<1, 1024>>>(deg, rowoff, cursor);
    scatter_kernel<<<(E_EDGES + 255) / 256, 256>>>(dst, cursor, perm);

    // node input projection + edge-chain collapse
    node_in_kernel<<<(N_NODES * HID + 255) / 256, 256>>>(x, node_W, node_b, h);
    precompute_V_kernel<<<1, 256>>>(edge_W, edge_b, We, Weu, beu, V);

    dim3 gN((HID + BN - 1) / BN, (N_NODES + BM - 1) / BM);   // (2, 235)

    for (int i = 0; i < NLAYERS; i++) {
        const float* Wl_i  = Wl  + (size_t)i * HID * HID;
        const float* Wr_i  = Wr  + (size_t)i * HID * HID;
        const float* bl_i  = bl  + i * HID;
        const float* br_i  = br  + i * HID;
        const float* att_i = att + (size_t)i * HID;
        const float* V_i   = V   + (size_t)i * 11 * HID;

        gemm_tf32x3_kernel<<<gN, 256>>>(h, Wl_i, bl_i, xl, N_NODES, HID, HID, 0);
        gemm_tf32x3_kernel<<<gN, 256>>>(h, Wr_i, br_i, xr, N_NODES, HID, HID, 0);

        attn_kernel<<<(N_NODES + 7) / 8, 256>>>(rowoff, perm, src, xl, xr, edge_attr,
                                                V_i, att_i,
                                                conv_b + i * HID, bn_rm + i * HID,
                                                bn_rv + i * HID, bn_g + i * HID,
                                                bn_b + i * HID, h, lg, (i >= 1) ? 1 : 0);
    }

    // output MLP
    dim3 gO(1, (N_NODES + BM - 1) / BM);
    gemm_tf32x3_kernel<<<gO, 256>>>(h, out_W1, out_b1, mlp, N_NODES, HID, 128, 1);
    out2_kernel<<<(N_NODES + 7) / 8, 256>>>(mlp, out_W2, out_b2, out);
}

// round 7
// speedup vs baseline: 5.9586x; 1.0512x over previous
#include <cuda_runtime.h>
#include <cuda_bf16.h>
#include <cstddef>
#include <cstdint>

#define N_NODES 30000
#define E_EDGES 480000
#define HID 256
#define HEADS 8
#define NLAYERS 6
#define NODE_IN 13
#define EDGE_IN 10

// ---------------- static device scratch (no allocations allowed) ----------------
__device__ float g_h   [N_NODES * HID];
__device__ float g_xl  [N_NODES * HID];
__device__ float g_xr  [N_NODES * HID];
__device__ float g_mlp [N_NODES * 128];
__device__ float g_V   [NLAYERS * 11 * HID];   // rows 0..9: edge_attr coeffs; row 10: const
__device__ int   g_deg [N_NODES];
__device__ int   g_rowoff[N_NODES + 1];
__device__ int   g_cursor[N_NODES];
__device__ int   g_perm[E_EDGES];

// ---------------- CSR build ----------------
__global__ void zero_int_kernel(int* p, int n) {
    int i = blockIdx.x * blockDim.x + threadIdx.x;
    if (i < n) p[i] = 0;
}

__global__ void count_kernel(const int* __restrict__ dst, int* __restrict__ deg) {
    int e = blockIdx.x * blockDim.x + threadIdx.x;
    if (e < E_EDGES) atomicAdd(&deg[dst[e]], 1);
}

__global__ void scan_kernel(const int* __restrict__ deg, int* __restrict__ rowoff,
                            int* __restrict__ cursor) {
    __shared__ int s[1024];
    int tid = threadIdx.x;
    const int CH = (N_NODES + 1023) / 1024;  // 30
    int base = tid * CH;
    int sum = 0;
    for (int i = 0; i < CH; i++) {
        int idx = base + i;
        if (idx < N_NODES) sum += deg[idx];
    }
    s[tid] = sum;
    __syncthreads();
    for (int off = 1; off < 1024; off <<= 1) {
        int v = (tid >= off) ? s[tid - off] : 0;
        __syncthreads();
        s[tid] += v;
        __syncthreads();
    }
    int run = s[tid] - sum;  // exclusive prefix
    for (int i = 0; i < CH; i++) {
        int idx = base + i;
        if (idx < N_NODES) {
            rowoff[idx] = run;
            cursor[idx] = run;
            run += deg[idx];
        }
    }
    if (tid == 1023) rowoff[N_NODES] = run;
}

__global__ void scatter_kernel(const int* __restrict__ dst, int* __restrict__ cursor,
                               int* __restrict__ perm) {
    int e = blockIdx.x * blockDim.x + threadIdx.x;
    if (e < E_EDGES) {
        int p = atomicAdd(&cursor[dst[e]], 1);
        perm[p] = e;
    }
}

// ---------------- node input projection ----------------
__global__ void node_in_kernel(const float* __restrict__ x, const float* __restrict__ W,
                               const float* __restrict__ b, float* __restrict__ h) {
    int idx = blockIdx.x * blockDim.x + threadIdx.x;
    if (idx >= N_NODES * HID) return;
    int r = idx >> 8, c = idx & 255;
    float s = b[c];
#pragma unroll
    for (int k = 0; k < NODE_IN; k++) s += x[r * NODE_IN + k] * W[k * HID + c];
    h[idx] = s;
}

// ---------------- edge-chain collapse: V_l = Uaug_l @ We_l, Uaug_{l+1} = Uaug_l @ Weu_l (+beu) ----------------
__global__ void precompute_V_kernel(const float* __restrict__ edge_W, const float* __restrict__ edge_b,
                                    const float* __restrict__ We, const float* __restrict__ Weu,
                                    const float* __restrict__ beu, float* __restrict__ V) {
    __shared__ float U[11][HID];
    int c = threadIdx.x;  // 0..255
    for (int k = 0; k < EDGE_IN; k++) U[k][c] = edge_W[k * HID + c];
    U[10][c] = edge_b[c];
    __syncthreads();
    for (int l = 0; l < NLAYERS; l++) {
        const float* WeL  = We  + (size_t)l * HID * HID;
        const float* WeuL = Weu + (size_t)l * HID * HID;
        float accV[11], accU[11];
#pragma unroll
        for (int k = 0; k < 11; k++) { accV[k] = 0.f; accU[k] = 0.f; }
        for (int j = 0; j < HID; j++) {
            float we  = WeL [j * HID + c];
            float weu = WeuL[j * HID + c];
#pragma unroll
            for (int k = 0; k < 11; k++) {
                float u = U[k][j];
                accV[k] += u * we;
                accU[k] += u * weu;
            }
        }
        accU[10] += beu[l * HID + c];
#pragma unroll
        for (int k = 0; k < 11; k++) V[((size_t)l * 11 + k) * HID + c] = accV[k];
        __syncthreads();
#pragma unroll
        for (int k = 0; k < 11; k++) U[k][c] = accU[k];
        __syncthreads();
    }
}

// ---------------- 3xTF32 tensor-core GEMM (near-fp32 accuracy) ----------------
#define BM 128
#define BN 128
#define BK 16
#define AS_STRIDE 20
#define BS_STRIDE 136

__device__ __forceinline__ uint32_t f2tf(float f) {
    uint32_t u;
    asm("cvt.rna.tf32.f32 %0, %1;" : "=r"(u) : "f"(f));
    return u;
}

__device__ __forceinline__ void mma_tf32(float* c, const uint32_t* a, uint32_t b0, uint32_t b1) {
    asm("mma.sync.aligned.m16n8k8.row.col.f32.tf32.tf32.f32 "
        "{%0,%1,%2,%3},{%4,%5,%6,%7},{%8,%9},{%0,%1,%2,%3};"
        : "+f"(c[0]), "+f"(c[1]), "+f"(c[2]), "+f"(c[3])
        : "r"(a[0]), "r"(a[1]), "r"(a[2]), "r"(a[3]), "r"(b0), "r"(b1));
}

__device__ __forceinline__ void split_tf(float f, uint32_t& hi, uint32_t& lo) {
    hi = f2tf(f);
    lo = f2tf(f - __uint_as_float(hi));
}

__global__ __launch_bounds__(256, 2)
void gemm_tf32x3_kernel(const float* __restrict__ A, const float* __restrict__ B,
                        const float* __restrict__ bias, float* __restrict__ C,
                        int M, int K, int Nc, int act) {
    __shared__ uint32_t AsH[BM * AS_STRIDE], AsL[BM * AS_STRIDE];
    __shared__ uint32_t BsH[BK * BS_STRIDE], BsL[BK * BS_STRIDE];

    int tid = threadIdx.x;
    int lane = tid & 31, warp = tid >> 5;
    int warpM = warp & 3, warpN = warp >> 2;  // 4 x 2
    int rowBase = blockIdx.y * BM;
    int colBase = blockIdx.x * BN;
    int gid = lane >> 2, tig = lane & 3;

    float acc[2][8][4];
#pragma unroll
    for (int mt = 0; mt < 2; mt++)
#pragma unroll
        for (int nt = 0; nt < 8; nt++)
#pragma unroll
            for (int i = 0; i < 4; i++) acc[mt][nt][i] = 0.f;

    for (int k0 = 0; k0 < K; k0 += BK) {
        // stage A [128 x 16]
#pragma unroll
        for (int i = 0; i < 2; i++) {
            int idx = tid + i * 256;
            int row = idx >> 2, q = idx & 3;
            int gr = rowBase + row;
            float4 v = make_float4(0.f, 0.f, 0.f, 0.f);
            if (gr < M) v = *(const float4*)(A + (size_t)gr * K + k0 + q * 4);
            uint32_t h0, l0, h1, l1, h2, l2, h3, l3;
            split_tf(v.x, h0, l0); split_tf(v.y, h1, l1);
            split_tf(v.z, h2, l2); split_tf(v.w, h3, l3);
            uint32_t* ph = &AsH[row * AS_STRIDE + q * 4];
            uint32_t* pl = &AsL[row * AS_STRIDE + q * 4];
            ph[0] = h0; ph[1] = h1; ph[2] = h2; ph[3] = h3;
            pl[0] = l0; pl[1] = l1; pl[2] = l2; pl[3] = l3;
        }
        // stage B [16 x 128]
#pragma unroll
        for (int i = 0; i < 2; i++) {
            int idx = tid + i * 256;
            int row = idx >> 5, q = idx & 31;
            float4 v = *(const float4*)(B + (size_t)(k0 + row) * Nc + colBase + q * 4);
            uint32_t h0, l0, h1, l1, h2, l2, h3, l3;
            split_tf(v.x, h0, l0); split_tf(v.y, h1, l1);
            split_tf(v.z, h2, l2); split_tf(v.w, h3, l3);
            uint32_t* ph = &BsH[row * BS_STRIDE + q * 4];
            uint32_t* pl = &BsL[row * BS_STRIDE + q * 4];
            ph[0] = h0; ph[1] = h1; ph[2] = h2; ph[3] = h3;
            pl[0] = l0; pl[1] = l1; pl[2] = l2; pl[3] = l3;
        }
        __syncthreads();

#pragma unroll
        for (int kk = 0; kk < 2; kk++) {
            int ko = kk * 8;
            uint32_t afh[2][4], afl[2][4];
#pragma unroll
            for (int mt = 0; mt < 2; mt++) {
                int r = warpM * 32 + mt * 16 + gid;
                afh[mt][0] = AsH[r * AS_STRIDE + ko + tig];
                afh[mt][1] = AsH[(r + 8) * AS_STRIDE + ko + tig];
                afh[mt][2] = AsH[r * AS_STRIDE + ko + tig + 4];
                afh[mt][3] = AsH[(r + 8) * AS_STRIDE + ko + tig + 4];
                afl[mt][0] = AsL[r * AS_STRIDE + ko + tig];
                afl[mt][1] = AsL[(r + 8) * AS_STRIDE + ko + tig];
                afl[mt][2] = AsL[r * AS_STRIDE + ko + tig + 4];
                afl[mt][3] = AsL[(r + 8) * AS_STRIDE + ko + tig + 4];
            }
#pragma unroll
            for (int nt = 0; nt < 8; nt++) {
                int n = warpN * 64 + nt * 8 + gid;
                uint32_t bh0 = BsH[(ko + tig) * BS_STRIDE + n];
                uint32_t bh1 = BsH[(ko + tig + 4) * BS_STRIDE + n];
                uint32_t bl0 = BsL[(ko + tig) * BS_STRIDE + n];
                uint32_t bl1 = BsL[(ko + tig + 4) * BS_STRIDE + n];
#pragma unroll
                for (int mt = 0; mt < 2; mt++) {
                    mma_tf32(acc[mt][nt], afh[mt], bh0, bh1);  // hi*hi
                    mma_tf32(acc[mt][nt], afh[mt], bl0, bl1);  // hi*lo
                    mma_tf32(acc[mt][nt], afl[mt], bh0, bh1);  // lo*hi
                }
            }
        }
        __syncthreads();
    }

#pragma unroll
    for (int mt = 0; mt < 2; mt++) {
        int r0 = rowBase + warpM * 32 + mt * 16 + gid;
        int r1 = r0 + 8;
#pragma unroll
        for (int nt = 0; nt < 8; nt++) {
            int c0 = colBase + warpN * 64 + nt * 8 + tig * 2;
            float v0 = acc[mt][nt][0], v1 = acc[mt][nt][1];
            float v2 = acc[mt][nt][2], v3 = acc[mt][nt][3];
            if (bias) {
                float b0 = bias[c0], b1 = bias[c0 + 1];
                v0 += b0; v1 += b1; v2 += b0; v3 += b1;
            }
            if (act) {
                v0 = (v0 >= 0.f) ? v0 : 0.01f * v0;
                v1 = (v1 >= 0.f) ? v1 : 0.01f * v1;
                v2 = (v2 >= 0.f) ? v2 : 0.01f * v2;
                v3 = (v3 >= 0.f) ? v3 : 0.01f * v3;
            }
            if (r0 < M) *(float2*)(C + (size_t)r0 * Nc + c0) = make_float2(v0, v1);
            if (r1 < M) *(float2*)(C + (size_t)r1 * Nc + c0) = make_float2(v2, v3);
        }
    }
}

// ---------------- fused attention (one pass, online softmax) ----------------
// One warp per destination node. ep reconstructed on the fly from V (11x256 in smem).
// Per 4-lane head group: running (mx, den); per lane: acc[8] for its 8 channels.
__global__ __launch_bounds__(256)
void attn_kernel(const int* __restrict__ rowoff, const int* __restrict__ perm,
                 const int* __restrict__ src, const float* __restrict__ xl,
                 const float* __restrict__ xr, const float* __restrict__ eattr,
                 const float* __restrict__ V_l, const float* __restrict__ att_l,
                 const float* __restrict__ conv_b, const float* __restrict__ rm,
                 const float* __restrict__ rv, const float* __restrict__ gg,
                 const float* __restrict__ gb, float* __restrict__ h,
                 int add_res) {
    __shared__ float sV[11 * HID];
    __shared__ float satt[HID];
    int tid = threadIdx.x;
    satt[tid] = att_l[tid];
    for (int i = tid; i < 11 * HID; i += 256) sV[i] = V_l[i];
    __syncthreads();

    int warp = tid >> 5, lane = tid & 31;
    int n = blockIdx.x * 8 + warp;
    if (n >= N_NODES) return;
    int beg = rowoff[n], end = rowoff[n + 1];
    int cb = lane * 8;

    float4 xr0 = *(const float4*)(xr + (size_t)n * HID + cb);
    float4 xr1 = *(const float4*)(xr + (size_t)n * HID + cb + 4);
    float4 at0 = *(const float4*)&satt[cb];
    float4 at1 = *(const float4*)&satt[cb + 4];
    float4 vc0 = *(const float4*)&sV[10 * HID + cb];      // constant term
    float4 vc1 = *(const float4*)&sV[10 * HID + cb + 4];

    float mx = -1e30f, den = 0.f;
    float acc[8] = {0.f, 0.f, 0.f, 0.f, 0.f, 0.f, 0.f, 0.f};

    for (int j = beg; j < end; j++) {
        int e = perm[j];
        int s = src[e];
        const float* ept = eattr + (size_t)e * EDGE_IN;
        const float4* pl = (const float4*)(xl + (size_t)s * HID + cb);
        float4 l0 = pl[0], l1 = pl[1];
        float ep[8] = {vc0.x, vc0.y, vc0.z, vc0.w, vc1.x, vc1.y, vc1.z, vc1.w};
#pragma unroll
        for (int k = 0; k < EDGE_IN; k++) {
            float ev = __ldg(ept + k);
            const float4* pv = (const float4*)&sV[k * HID + cb];
            float4 w0 = pv[0], w1 = pv[1];
            ep[0] += ev * w0.x; ep[1] += ev * w0.y; ep[2] += ev * w0.z; ep[3] += ev * w0.w;
            ep[4] += ev * w1.x; ep[5] += ev * w1.y; ep[6] += ev * w1.z; ep[7] += ev * w1.w;
        }
        float m0 = l0.x + xr0.x + ep[0];
        float m1 = l0.y + xr0.y + ep[1];
        float m2 = l0.z + xr0.z + ep[2];
        float m3 = l0.w + xr0.w + ep[3];
        float m4 = l1.x + xr1.x + ep[4];
        float m5 = l1.y + xr1.y + ep[5];
        float m6 = l1.z + xr1.z + ep[6];
        float m7 = l1.w + xr1.w + ep[7];
        m0 = (m0 >= 0.f) ? m0 : 0.2f * m0;  m1 = (m1 >= 0.f) ? m1 : 0.2f * m1;
        m2 = (m2 >= 0.f) ? m2 : 0.2f * m2;  m3 = (m3 >= 0.f) ? m3 : 0.2f * m3;
        m4 = (m4 >= 0.f) ? m4 : 0.2f * m4;  m5 = (m5 >= 0.f) ? m5 : 0.2f * m5;
        m6 = (m6 >= 0.f) ? m6 : 0.2f * m6;  m7 = (m7 >= 0.f) ? m7 : 0.2f * m7;
        float sum = m0 * at0.x + m1 * at0.y + m2 * at0.z + m3 * at0.w
                  + m4 * at1.x + m5 * at1.y + m6 * at1.z + m7 * at1.w;
        sum += __shfl_xor_sync(0xffffffffu, sum, 1);
        sum += __shfl_xor_sync(0xffffffffu, sum, 2);     // head logit in all 4 group lanes

        // online softmax update (exact rescale; exp(0)==1 when mx unchanged)
        float mnew = fmaxf(mx, sum);
        float corr = __expf(mx - mnew);
        float w = __expf(sum - mnew);
        den = den * corr + w;
        acc[0] = acc[0] * corr + w * l0.x;
        acc[1] = acc[1] * corr + w * l0.y;
        acc[2] = acc[2] * corr + w * l0.z;
        acc[3] = acc[3] * corr + w * l0.w;
        acc[4] = acc[4] * corr + w * l1.x;
        acc[5] = acc[5] * corr + w * l1.y;
        acc[6] = acc[6] * corr + w * l1.z;
        acc[7] = acc[7] * corr + w * l1.w;
        mx = mnew;
    }

    float inv = 1.0f / (den + 1e-16f);

    // epilogue: conv bias + BN + leaky + residual
#pragma unroll
    for (int k = 0; k < 8; k++) {
        int c = cb + k;
        float v = acc[k] * inv + conv_b[c];
        v = (v - rm[c]) * rsqrtf(rv[c] + 1e-5f) * gg[c] + gb[c];
        v = (v >= 0.f) ? v : 0.01f * v;
        if (add_res) v += h[(size_t)n * HID + c];
        h[(size_t)n * HID + c] = v;
    }
}

// ---------------- final projection: [N,128] @ [128,1] ----------------
__global__ void out2_kernel(const float* __restrict__ mlp, const float* __restrict__ W2,
                            const float* __restrict__ b2, float* __restrict__ out) {
    int warp = threadIdx.x >> 5, lane = threadIdx.x & 31;
    int n = blockIdx.x * 8 + warp;
    if (n >= N_NODES) return;
    float4 m = *(const float4*)(mlp + (size_t)n * 128 + lane * 4);
    float4 w = *(const float4*)(W2 + lane * 4);
    float s = m.x * w.x + m.y * w.y + m.z * w.z + m.w * w.w;
#pragma unroll
    for (int off = 16; off; off >>= 1) s += __shfl_xor_sync(0xffffffffu, s, off);
    if (lane == 0) out[n] = s + b2[0];
}

// ---------------- launcher ----------------
static float* sym_f(const void* symbol) {
    void* p = nullptr;
    cudaGetSymbolAddress(&p, symbol);
    return (float*)p;
}
static int* sym_i(const void* symbol) {
    void* p = nullptr;
    cudaGetSymbolAddress(&p, symbol);
    return (int*)p;
}

extern "C" void kernel_launch(void* const* d_in, const int* in_sizes, int n_in,
                              void* d_out, int out_size) {
    const float* x        = (const float*)d_in[0];
    const int*   ei       = (const int*)  d_in[1];
    const float* edge_attr= (const float*)d_in[2];
    const float* node_W   = (const float*)d_in[3];
    const float* node_b   = (const float*)d_in[4];
    const float* edge_W   = (const float*)d_in[5];
    const float* edge_b   = (const float*)d_in[6];
    const float* Wl       = (const float*)d_in[7];
    const float* bl       = (const float*)d_in[8];
    const float* Wr       = (const float*)d_in[9];
    const float* br       = (const float*)d_in[10];
    const float* We       = (const float*)d_in[11];
    const float* att      = (const float*)d_in[12];
    const float* conv_b   = (const float*)d_in[13];
    const float* Weu      = (const float*)d_in[14];
    const float* beu      = (const float*)d_in[15];
    const float* bn_g     = (const float*)d_in[16];
    const float* bn_b     = (const float*)d_in[17];
    const float* bn_rm    = (const float*)d_in[18];
    const float* bn_rv    = (const float*)d_in[19];
    const float* out_W1   = (const float*)d_in[20];
    const float* out_b1   = (const float*)d_in[21];
    const float* out_W2   = (const float*)d_in[22];
    const float* out_b2   = (const float*)d_in[23];
    float* out = (float*)d_out;

    float* h   = sym_f(g_h);
    float* xl  = sym_f(g_xl);
    float* xr  = sym_f(g_xr);
    float* mlp = sym_f(g_mlp);
    float* V   = sym_f(g_V);
    int* deg    = sym_i(g_deg);
    int* rowoff = sym_i(g_rowoff);
    int* cursor = sym_i(g_cursor);
    int* perm   = sym_i(g_perm);

    const int* src = ei;
    const int* dst = ei + E_EDGES;

    // CSR build
    zero_int_kernel<<<(N_NODES + 255) / 256, 256>>>(deg, N_NODES);
    count_kernel<<<(E_EDGES + 255) / 256, 256>>>(dst, deg);
    scan_kernel<<<1, 1024>>>(deg, rowoff, cursor);
    scatter_kernel<<<(E_EDGES + 255) / 256, 256>>>(dst, cursor, perm);

    // node input projection + edge-chain collapse
    node_in_kernel<<<(N_NODES * HID + 255) / 256, 256>>>(x, node_W, node_b, h);
    precompute_V_kernel<<<1, 256>>>(edge_W, edge_b, We, Weu, beu, V);

    dim3 gN((HID + BN - 1) / BN, (N_NODES + BM - 1) / BM);   // (2, 235)

    for (int i = 0; i < NLAYERS; i++) {
        const float* Wl_i  = Wl  + (size_t)i * HID * HID;
        const float* Wr_i  = Wr  + (size_t)i * HID * HID;
        const float* bl_i  = bl  + i * HID;
        const float* br_i  = br  + i * HID;
        const float* att_i = att + (size_t)i * HID;
        const float* V_i   = V   + (size_t)i * 11 * HID;

        gemm_tf32x3_kernel<<<gN, 256>>>(h, Wl_i, bl_i, xl, N_NODES, HID, HID, 0);
        gemm_tf32x3_kernel<<<gN, 256>>>(h, Wr_i, br_i, xr, N_NODES, HID, HID, 0);

        attn_kernel<<<(N_NODES + 7) / 8, 256>>>(rowoff, perm, src, xl, xr, edge_attr,
                                                V_i, att_i,
                                                conv_b + i * HID, bn_rm + i * HID,
                                                bn_rv + i * HID, bn_g + i * HID,
                                                bn_b + i * HID, h, (i >= 1) ? 1 : 0);
    }

    // output MLP
    dim3 gO(1, (N_NODES + BM - 1) / BM);
    gemm_tf32x3_kernel<<<gO, 256>>>(h, out_W1, out_b1, mlp, N_NODES, HID, 128, 1);
    out2_kernel<<<(N_NODES + 7) / 8, 256>>>(mlp, out_W2, out_b2, out);
}